// round 15
// baseline (speedup 1.0000x reference)
#include <cuda_runtime.h>
#include <cstdint>

// ============================================================================
// Bit-exact JAX threefry2x32 (partitionable) — rel_err = 0.0 verified R2-R14.
// R15 = R14 (best: 323.7us) with phase 2 restructured: ins-flag draws moved to
//   FIXED per-lane indices inside phase 1 (3 chains, one loop, no scan
//   dependency), then each lane gathers its flag window with 2 SHFL + funnel
//   shift. Kills phase-2's serial j-chain + per-iter bookkeeping (~80 alu) and
//   the scan1->phase2 critical-path serialization.
// ============================================================================

#define FULLM 0xffffffffu

struct TKey { uint32_t a, b, c; };

__device__ __forceinline__ TKey mk_key(uint32_t k0, uint32_t k1) {
    TKey k; k.a = k0; k.b = k1; k.c = k0 ^ k1 ^ 0x1BD11BDAu; return k;
}

// ---- plain threefry (setup kernel only)
#define TF_ROUND(x0, x1, r) { x0 += x1; x1 = __funnelshift_l(x1, x1, (r)); x1 ^= x0; }
#define TF_R4A(x0, x1) { TF_ROUND(x0,x1,13) TF_ROUND(x0,x1,15) TF_ROUND(x0,x1,26) TF_ROUND(x0,x1,6) }
#define TF_R4B(x0, x1) { TF_ROUND(x0,x1,17) TF_ROUND(x0,x1,29) TF_ROUND(x0,x1,16) TF_ROUND(x0,x1,24) }

__device__ __forceinline__ void tf_pair(const TKey k, uint32_t c0, uint32_t c1,
                                        uint32_t& o0, uint32_t& o1) {
    uint32_t x0 = c0 + k.a, x1 = c1 + k.b;
    TF_R4A(x0, x1); x0 += k.b; x1 += k.c + 1u;
    TF_R4B(x0, x1); x0 += k.c; x1 += k.a + 2u;
    TF_R4A(x0, x1); x0 += k.a; x1 += k.b + 3u;
    TF_R4B(x0, x1); x0 += k.b; x1 += k.c + 4u;
    TF_R4A(x0, x1); x0 += k.c; x1 += k.a + 5u;
    o0 = x0; o1 = x1;
}

// ---- add on the IMAD pipe (`one` = opaque runtime 1)
__device__ __forceinline__ uint32_t addf(uint32_t a, uint32_t b, uint32_t one) {
    uint32_t d;
    asm("mad.lo.u32 %0, %1, %2, %3;" : "=r"(d) : "r"(a), "r"(one), "r"(b));
    return d;
}

// ---- shift-and-accumulate on the IMAD pipe: d = a * mult + b
__device__ __forceinline__ uint32_t madp(uint32_t a, uint32_t mult, uint32_t b) {
    uint32_t d;
    asm("mad.lo.u32 %0, %1, %2, %3;" : "=r"(d) : "r"(a), "r"(mult), "r"(b));
    return d;
}

struct TSched {
    uint32_t a, b, c;
    uint32_t c1, a2, b3, c4, a5;
};

__device__ __forceinline__ TSched mk_sched(uint32_t a, uint32_t b, uint32_t c) {
    TSched s; s.a = a; s.b = b; s.c = c;
    s.c1 = c + 1u; s.a2 = a + 2u; s.b3 = b + 3u; s.c4 = c + 4u; s.a5 = a + 5u;
    return s;
}

#define TFF_ROUND(x0, x1, r) { x0 = addf(x0, x1, one); x1 = __funnelshift_l(x1, x1, (r)); x1 ^= x0; }
#define TFF_R4A(x0, x1) { TFF_ROUND(x0,x1,13) TFF_ROUND(x0,x1,15) TFF_ROUND(x0,x1,26) TFF_ROUND(x0,x1,6) }
#define TFF_R4B(x0, x1) { TFF_ROUND(x0,x1,17) TFF_ROUND(x0,x1,29) TFF_ROUND(x0,x1,16) TFF_ROUND(x0,x1,24) }

// threefry2x32 at counter (0, idx): 20 SHF + 21 LOP3 (alu), 31 IMAD
__device__ __forceinline__ uint32_t tff_bits(const TSched k, uint32_t idx, uint32_t one) {
    uint32_t x0 = k.a, x1 = addf(idx, k.b, one);
    TFF_R4A(x0, x1); x0 = addf(x0, k.b, one); x1 = addf(x1, k.c1, one);
    TFF_R4B(x0, x1); x0 = addf(x0, k.c, one); x1 = addf(x1, k.a2, one);
    TFF_R4A(x0, x1); x0 = addf(x0, k.a, one); x1 = addf(x1, k.b3, one);
    TFF_R4B(x0, x1); x0 = addf(x0, k.b, one); x1 = addf(x1, k.c4, one);
    TFF_R4A(x0, x1); x0 = addf(x0, k.c, one); x1 = addf(x1, k.a5, one);
    return x0 ^ x1;
}

// Pre-shifted threshold: uniform(bits) < e  <=>  bits < (ceil(e*2^23) << 9).
__device__ __forceinline__ uint32_t thresh_shifted(float e) {
    return ((uint32_t)ceil((double)e * 8388608.0)) << 9;
}

// SWAR: per-2-bit-field (a + b) mod 4 over all 16 fields at once (4 LOP3).
__device__ __forceinline__ uint32_t add2bit_mod4(uint32_t a, uint32_t b) {
    const uint32_t t = a ^ b;
    const uint32_t cy = (a & b) & 0x55555555u;
    return t ^ (cy << 1);
}

// ============================================================================
// Per-channel key cache (keys depend only on channel c).
// ============================================================================

__device__ uint32_t g_keys[4][16];

__global__ void key_setup_kernel() {
    const int c = threadIdx.x;
    if (c >= 4) return;
    uint32_t t0, t1;
    const TKey root = mk_key(0u, 42u);
    tf_pair(root, 0u, (uint32_t)c, t0, t1);
    const TKey kc = mk_key(t0, t1);

    tf_pair(kc, 0u, 0u, t0, t1); const TKey s1 = mk_key(t0, t1);
    tf_pair(kc, 0u, 1u, t0, t1); const TKey s2 = mk_key(t0, t1);
    tf_pair(kc, 0u, 2u, t0, t1); const TKey s3 = mk_key(t0, t1);

    tf_pair(s1, 0u, 0u, t0, t1); const TKey sub_a = mk_key(t0, t1);
    tf_pair(sub_a, 0u, 1u, t0, t1); const TKey k_subdata = mk_key(t0, t1);
    tf_pair(s1, 0u, 1u, t0, t1); const TKey k_submask = mk_key(t0, t1);

    tf_pair(s3, 0u, 0u, t0, t1); const TKey k_insflag = mk_key(t0, t1);
    tf_pair(s3, 0u, 1u, t0, t1); const TKey ins_b = mk_key(t0, t1);
    tf_pair(ins_b, 0u, 1u, t0, t1); const TKey k_inssym = mk_key(t0, t1);

    uint32_t* kp = g_keys[c];
    kp[0] = k_submask.a; kp[1] = k_submask.b; kp[2] = k_submask.c;
    kp[3] = s2.a;        kp[4] = s2.b;        kp[5] = s2.c;
    kp[6] = k_subdata.a; kp[7] = k_subdata.b; kp[8] = k_subdata.c;
    kp[9] = k_insflag.a; kp[10] = k_insflag.b; kp[11] = k_insflag.c;
    kp[12] = k_inssym.a; kp[13] = k_inssym.b; kp[14] = k_inssym.c;
}

// ============================================================================
// Warp-per-(row, channel); lane owns 16 contiguous elements, 2-bit packed.
// ============================================================================

__global__ void __launch_bounds__(128)
channel_warp_kernel(const float* __restrict__ x, float* __restrict__ out, int B) {
    const int gw = (int)((blockIdx.x * blockDim.x + threadIdx.x) >> 5);
    const int lane = threadIdx.x & 31;
    if (gw >= B * 4) return;
    const int c = gw & 3;
    const int b = gw >> 2;

    const uint32_t KsubS = thresh_shifted(0.02f);
    const uint32_t KdelS = thresh_shifted(0.01f);
    const uint32_t KinsS = thresh_shifted(0.01f);

    const uint32_t* kp = g_keys[c];
    const uint32_t one = (kp[0] >> 31) | 1u;       // opaque runtime 1
    const TSched kSubM = mk_sched(kp[0], kp[1], kp[2]);
    const TSched kDel  = mk_sched(kp[3], kp[4], kp[5]);
    const TSched kInsF = mk_sched(kp[9], kp[10], kp[11]);

    // ---- phase 1: THREE chains at fixed indices (no scan dependency).
    //   sub/del over (B,512) at base+i; ins-flag over (B,514) at fixed
    //   per-lane slice ibase+i (covers all compacted positions [0,512)).
    const uint32_t base    = (uint32_t)b * 512u + (uint32_t)lane * 16u;
    const uint32_t insbase = (uint32_t)b * 514u;
    const uint32_t ibase   = insbase + (uint32_t)lane * 16u;
    uint32_t keepmask = 0u, subneed = 0u, flags16 = 0u;
    {
        uint32_t bit = 1u;
        #pragma unroll 2
        for (int i = 0; i < 16; i++) {
            const uint32_t bs = tff_bits(kSubM, base + (uint32_t)i, one);
            const uint32_t bd = tff_bits(kDel,  base + (uint32_t)i, one);
            const uint32_t bi = tff_bits(kInsF, ibase + (uint32_t)i, one);
            if (bs < KsubS)  subneed  |= bit;
            if (bd >= KdelS) keepmask |= bit;
            if (bi < KinsS)  flags16  |= bit;
            bit <<= 1;
        }
    }

    // ---- load input and pack to 2-bit codes (F2I + IMAD: fma pipe)
    uint32_t vpack = 0u;
    {
        const float4* __restrict__ xr4 =
            (const float4*)(x + (size_t)b * 512 + (size_t)lane * 16);
        #pragma unroll
        for (int q = 0; q < 4; q++) {
            const float4 f = xr4[q];
            const uint32_t c0 = (uint32_t)__float2int_rn(f.x);
            const uint32_t c1 = (uint32_t)__float2int_rn(f.y);
            const uint32_t c2 = (uint32_t)__float2int_rn(f.z);
            const uint32_t c3 = (uint32_t)__float2int_rn(f.w);
            vpack = madp(c0, (1u << (8 * q + 0)) * one, vpack);
            vpack = madp(c1, (1u << (8 * q + 2)) * one, vpack);
            vpack = madp(c2, (1u << (8 * q + 4)) * one, vpack);
            vpack = madp(c3, (1u << (8 * q + 6)) * one, vpack);
        }
    }

    // ---- deferred sub draws: per-lane bit loop, 2-bit packed deltas
    uint32_t subdelta = 0u;
    {
        const TSched kSubD = mk_sched(kp[6], kp[7], kp[8]);
        uint32_t m = subneed;
        while (m) {
            const int i = __ffs(m) - 1; m &= m - 1u;
            const uint32_t db = tff_bits(kSubD, base + (uint32_t)i, one);
            subdelta |= (db & 3u) << (2 * i);
        }
    }
    uint32_t pk = add2bit_mod4(vpack, subdelta);

    // ---- scan 1: exclusive scan of keep counts -> compacted offset (in-row)
    const int kn = __popc(keepmask);
    int incl = kn;
    #pragma unroll
    for (int d = 1; d < 32; d <<= 1) {
        const int nv = __shfl_up_sync(FULLM, incl, d);
        if (lane >= d) incl += nv;
    }
    const int ofs = incl - kn;     // 0..512

    // ---- gather my 16-bit ins-flag window starting at compacted pos `ofs`:
    // flag for compacted pos p lives in lane p>>4, bit p&15.
    uint32_t window;
    {
        const uint32_t s  = (uint32_t)ofs;
        const uint32_t sh = s & 15u;
        const uint32_t a  = __shfl_sync(FULLM, flags16, (int)(s >> 4) & 31);
        const uint32_t bw = __shfl_sync(FULLM, flags16, (int)((s >> 4) + 1u) & 31);
        window = ((a >> sh) | (bw << (16u - sh))) & 0xFFFFu;   // sh=0: bw<<16 drops out
    }
    // fired inserts among my kn kept elements (window bit r = keep-rank r)
    const uint32_t fired = window & ((1u << kn) - 1u);     // kn <= 16

    // ---- scan 2: output offsets
    const int myout = kn + __popc(fired);
    int incl2 = myout;
    #pragma unroll
    for (int d = 1; d < 32; d <<= 1) {
        const int nv = __shfl_up_sync(FULLM, incl2, d);
        if (lane >= d) incl2 += nv;
    }
    const int outofs = incl2 - myout;
    const int total_out = __shfl_sync(FULLM, incl2, 31);

    float* __restrict__ orow = out + ((size_t)b * 4 + (size_t)c) * 514;

    // ---- write kept elements; win advances one bit per KEPT element
    {
        int pos = outofs;
        uint32_t km = keepmask, win = window;
        #pragma unroll
        for (int i = 0; i < 16; i++) {
            const float vv = (float)(pk & 3u) + 1.0f;   // code in [0,3] exact
            const uint32_t kb = km & 1u;
            if (kb && pos < 514) orow[pos] = vv;
            pos += (int)(kb + (kb & win));
            win >>= kb; km >>= 1; pk >>= 2;
        }
    }

    // ---- inserted symbols: iterate fired bits by keep-rank r
    {
        const TSched kInsS2 = mk_sched(kp[12], kp[13], kp[14]);
        uint32_t m = fired;
        while (m) {
            const int r = __ffs(m) - 1; m &= m - 1u;
            const uint32_t j = insbase + (uint32_t)(ofs + r);
            const int pos = outofs + r + 1 + __popc(fired & ((1u << r) - 1u));
            const uint32_t sb = tff_bits(kInsS2, j, one);
            if (pos < 514) orow[pos] = (float)(sb & 3u) + 1.0f;
        }
    }

    // ---- tail padding: 0.0 (= -1 + 1)
    for (int p = total_out + lane; p < 514; p += 32) orow[p] = 0.0f;
}

extern "C" void kernel_launch(void* const* d_in, const int* in_sizes, int n_in,
                              void* d_out, int out_size) {
    const float* x = (const float*)d_in[0];   // segment_en [B, 512]
    float* out = (float*)d_out;               // [B, 4, 514] float32
    const int B = in_sizes[0] / 512;

    key_setup_kernel<<<1, 4>>>();

    const long long total_threads = (long long)B * 4 * 32;
    const int block = 128;
    const int grid = (int)((total_threads + block - 1) / block);
    channel_warp_kernel<<<grid, block>>>(x, out, B);
}

// round 16
// speedup vs baseline: 1.0038x; 1.0038x over previous
#include <cuda_runtime.h>
#include <cstdint>

// ============================================================================
// Bit-exact JAX threefry2x32 (partitionable) — rel_err = 0.0 verified R2-R15.
// FINAL (= R14, best measured 323.7us): warp-per-(row,channel), 2-bit packed
// values (F2I+IMAD pack on fma pipe), mad-forced threefry adds (IMAD pipe),
// SHF rotates, unroll-4 phase loops, deferred rare draws, load deferral,
// block=128. alu pipe ~93% saturated at the 48-hash/lane algorithmic floor;
// all further trims measured neutral or negative (R6,R7,R10,R11,R12,R15).
// ============================================================================

#define FULLM 0xffffffffu

struct TKey { uint32_t a, b, c; };

__device__ __forceinline__ TKey mk_key(uint32_t k0, uint32_t k1) {
    TKey k; k.a = k0; k.b = k1; k.c = k0 ^ k1 ^ 0x1BD11BDAu; return k;
}

// ---- plain threefry (setup kernel only)
#define TF_ROUND(x0, x1, r) { x0 += x1; x1 = __funnelshift_l(x1, x1, (r)); x1 ^= x0; }
#define TF_R4A(x0, x1) { TF_ROUND(x0,x1,13) TF_ROUND(x0,x1,15) TF_ROUND(x0,x1,26) TF_ROUND(x0,x1,6) }
#define TF_R4B(x0, x1) { TF_ROUND(x0,x1,17) TF_ROUND(x0,x1,29) TF_ROUND(x0,x1,16) TF_ROUND(x0,x1,24) }

__device__ __forceinline__ void tf_pair(const TKey k, uint32_t c0, uint32_t c1,
                                        uint32_t& o0, uint32_t& o1) {
    uint32_t x0 = c0 + k.a, x1 = c1 + k.b;
    TF_R4A(x0, x1); x0 += k.b; x1 += k.c + 1u;
    TF_R4B(x0, x1); x0 += k.c; x1 += k.a + 2u;
    TF_R4A(x0, x1); x0 += k.a; x1 += k.b + 3u;
    TF_R4B(x0, x1); x0 += k.b; x1 += k.c + 4u;
    TF_R4A(x0, x1); x0 += k.c; x1 += k.a + 5u;
    o0 = x0; o1 = x1;
}

// ---- add on the IMAD pipe (`one` = opaque runtime 1)
__device__ __forceinline__ uint32_t addf(uint32_t a, uint32_t b, uint32_t one) {
    uint32_t d;
    asm("mad.lo.u32 %0, %1, %2, %3;" : "=r"(d) : "r"(a), "r"(one), "r"(b));
    return d;
}

// ---- shift-and-accumulate on the IMAD pipe: d = a * mult + b  (mult = 2^k)
__device__ __forceinline__ uint32_t madp(uint32_t a, uint32_t mult, uint32_t b) {
    uint32_t d;
    asm("mad.lo.u32 %0, %1, %2, %3;" : "=r"(d) : "r"(a), "r"(mult), "r"(b));
    return d;
}

struct TSched {
    uint32_t a, b, c;
    uint32_t c1, a2, b3, c4, a5;   // k.c+1, k.a+2, k.b+3, k.c+4, k.a+5
};

__device__ __forceinline__ TSched mk_sched(uint32_t a, uint32_t b, uint32_t c) {
    TSched s; s.a = a; s.b = b; s.c = c;
    s.c1 = c + 1u; s.a2 = a + 2u; s.b3 = b + 3u; s.c4 = c + 4u; s.a5 = a + 5u;
    return s;
}

#define TFF_ROUND(x0, x1, r) { x0 = addf(x0, x1, one); x1 = __funnelshift_l(x1, x1, (r)); x1 ^= x0; }
#define TFF_R4A(x0, x1) { TFF_ROUND(x0,x1,13) TFF_ROUND(x0,x1,15) TFF_ROUND(x0,x1,26) TFF_ROUND(x0,x1,6) }
#define TFF_R4B(x0, x1) { TFF_ROUND(x0,x1,17) TFF_ROUND(x0,x1,29) TFF_ROUND(x0,x1,16) TFF_ROUND(x0,x1,24) }

// threefry2x32 at counter (0, idx): 20 SHF + 21 LOP3 (alu), 31 IMAD
__device__ __forceinline__ uint32_t tff_bits(const TSched k, uint32_t idx, uint32_t one) {
    uint32_t x0 = k.a, x1 = addf(idx, k.b, one);
    TFF_R4A(x0, x1); x0 = addf(x0, k.b, one); x1 = addf(x1, k.c1, one);
    TFF_R4B(x0, x1); x0 = addf(x0, k.c, one); x1 = addf(x1, k.a2, one);
    TFF_R4A(x0, x1); x0 = addf(x0, k.a, one); x1 = addf(x1, k.b3, one);
    TFF_R4B(x0, x1); x0 = addf(x0, k.b, one); x1 = addf(x1, k.c4, one);
    TFF_R4A(x0, x1); x0 = addf(x0, k.c, one); x1 = addf(x1, k.a5, one);
    return x0 ^ x1;
}

// Pre-shifted threshold: uniform(bits) < e  <=>  bits < (ceil(e*2^23) << 9).
__device__ __forceinline__ uint32_t thresh_shifted(float e) {
    return ((uint32_t)ceil((double)e * 8388608.0)) << 9;
}

// SWAR: per-2-bit-field (a + b) mod 4 over all 16 fields at once (4 LOP3).
__device__ __forceinline__ uint32_t add2bit_mod4(uint32_t a, uint32_t b) {
    const uint32_t t = a ^ b;
    const uint32_t cy = (a & b) & 0x55555555u;
    return t ^ (cy << 1);
}

// ============================================================================
// Per-channel key cache (keys depend only on channel c).
// ============================================================================

__device__ uint32_t g_keys[4][16];

__global__ void key_setup_kernel() {
    const int c = threadIdx.x;
    if (c >= 4) return;
    uint32_t t0, t1;
    const TKey root = mk_key(0u, 42u);
    tf_pair(root, 0u, (uint32_t)c, t0, t1);
    const TKey kc = mk_key(t0, t1);

    tf_pair(kc, 0u, 0u, t0, t1); const TKey s1 = mk_key(t0, t1);
    tf_pair(kc, 0u, 1u, t0, t1); const TKey s2 = mk_key(t0, t1);
    tf_pair(kc, 0u, 2u, t0, t1); const TKey s3 = mk_key(t0, t1);

    tf_pair(s1, 0u, 0u, t0, t1); const TKey sub_a = mk_key(t0, t1);
    tf_pair(sub_a, 0u, 1u, t0, t1); const TKey k_subdata = mk_key(t0, t1);
    tf_pair(s1, 0u, 1u, t0, t1); const TKey k_submask = mk_key(t0, t1);

    tf_pair(s3, 0u, 0u, t0, t1); const TKey k_insflag = mk_key(t0, t1);
    tf_pair(s3, 0u, 1u, t0, t1); const TKey ins_b = mk_key(t0, t1);
    tf_pair(ins_b, 0u, 1u, t0, t1); const TKey k_inssym = mk_key(t0, t1);

    uint32_t* kp = g_keys[c];
    kp[0] = k_submask.a; kp[1] = k_submask.b; kp[2] = k_submask.c;
    kp[3] = s2.a;        kp[4] = s2.b;        kp[5] = s2.c;
    kp[6] = k_subdata.a; kp[7] = k_subdata.b; kp[8] = k_subdata.c;
    kp[9] = k_insflag.a; kp[10] = k_insflag.b; kp[11] = k_insflag.c;
    kp[12] = k_inssym.a; kp[13] = k_inssym.b; kp[14] = k_inssym.c;
}

// ============================================================================
// Warp-per-(row, channel); lane owns 16 contiguous elements, 2-bit packed.
// ============================================================================

__global__ void __launch_bounds__(128)
channel_warp_kernel(const float* __restrict__ x, float* __restrict__ out, int B) {
    const int gw = (int)((blockIdx.x * blockDim.x + threadIdx.x) >> 5);
    const int lane = threadIdx.x & 31;
    if (gw >= B * 4) return;
    const int c = gw & 3;
    const int b = gw >> 2;

    const uint32_t KsubS = thresh_shifted(0.02f);
    const uint32_t KdelS = thresh_shifted(0.01f);
    const uint32_t KinsS = thresh_shifted(0.01f);

    const uint32_t* kp = g_keys[c];
    const uint32_t one = (kp[0] >> 31) | 1u;       // opaque runtime 1
    const TSched kSubM = mk_sched(kp[0], kp[1], kp[2]);
    const TSched kDel  = mk_sched(kp[3], kp[4], kp[5]);

    // ---- phase 1: sub-need + keep flags (unroll 4, ILP=8); no LDGs yet
    const uint32_t base = (uint32_t)b * 512u + (uint32_t)lane * 16u;
    uint32_t keepmask = 0u, subneed = 0u;
    {
        uint32_t bit = 1u;
        #pragma unroll 4
        for (int i = 0; i < 16; i++) {
            const uint32_t idx = base + (uint32_t)i;
            const uint32_t bs = tff_bits(kSubM, idx, one);
            const uint32_t bd = tff_bits(kDel,  idx, one);
            if (bs < KsubS)  subneed  |= bit;
            if (bd >= KdelS) keepmask |= bit;
            bit <<= 1;
        }
    }

    // ---- load input and pack to 2-bit codes (F2I + IMAD: all fma pipe).
    // One live register instead of 16; LDG latency hides behind sub/ins phases.
    uint32_t vpack = 0u;
    {
        const float4* __restrict__ xr4 =
            (const float4*)(x + (size_t)b * 512 + (size_t)lane * 16);
        #pragma unroll
        for (int q = 0; q < 4; q++) {
            const float4 f = xr4[q];
            const uint32_t c0 = (uint32_t)__float2int_rn(f.x);
            const uint32_t c1 = (uint32_t)__float2int_rn(f.y);
            const uint32_t c2 = (uint32_t)__float2int_rn(f.z);
            const uint32_t c3 = (uint32_t)__float2int_rn(f.w);
            vpack = madp(c0, (1u << (8 * q + 0)) * one, vpack);
            vpack = madp(c1, (1u << (8 * q + 2)) * one, vpack);
            vpack = madp(c2, (1u << (8 * q + 4)) * one, vpack);
            vpack = madp(c3, (1u << (8 * q + 6)) * one, vpack);
        }
    }

    // ---- deferred sub draws: per-lane bit loop, 2-bit packed deltas
    uint32_t subdelta = 0u;
    {
        const TSched kSubD = mk_sched(kp[6], kp[7], kp[8]);
        uint32_t m = subneed;
        while (m) {
            const int i = __ffs(m) - 1; m &= m - 1u;
            const uint32_t db = tff_bits(kSubD, base + (uint32_t)i, one);
            subdelta |= (db & 3u) << (2 * i);
        }
    }
    // ---- apply sub across all 16 fields at once (4 LOP3)
    uint32_t pk = add2bit_mod4(vpack, subdelta);

    // ---- scan 1: exclusive scan of keep counts -> compacted offset
    const int kn = __popc(keepmask);
    int incl = kn;
    #pragma unroll
    for (int d = 1; d < 32; d <<= 1) {
        const int nv = __shfl_up_sync(FULLM, incl, d);
        if (lane >= d) incl += nv;
    }
    const int ofs = incl - kn;

    // ---- phase 2: ins flags at compacted indices (iterative j, unroll 4)
    const uint32_t insbase = (uint32_t)b * 514u;
    uint32_t insmask = 0u;
    {
        const TSched kInsF = mk_sched(kp[9], kp[10], kp[11]);
        uint32_t km = keepmask, bit = 1u;
        uint32_t j = insbase + (uint32_t)ofs;
        #pragma unroll 4
        for (int i = 0; i < 16; i++) {
            const uint32_t bi = tff_bits(kInsF, j, one);
            if (bi < KinsS) insmask |= bit;
            j += km & 1u; km >>= 1; bit <<= 1;
        }
    }
    insmask &= keepmask;

    // ---- scan 2: output offsets
    const int myout = kn + __popc(insmask);
    int incl2 = myout;
    #pragma unroll
    for (int d = 1; d < 32; d <<= 1) {
        const int nv = __shfl_up_sync(FULLM, incl2, d);
        if (lane >= d) incl2 += nv;
    }
    const int outofs = incl2 - myout;
    const int total_out = __shfl_sync(FULLM, incl2, 31);

    float* __restrict__ orow = out + ((size_t)b * 4 + (size_t)c) * 514;

    // ---- write kept elements: extract 2-bit code -> I2F + FADD (fma pipe)
    {
        int pos = outofs;
        uint32_t km = keepmask, im = insmask;
        #pragma unroll
        for (int i = 0; i < 16; i++) {
            const float vv = (float)(pk & 3u) + 1.0f;   // code in [0,3] exact
            if ((km & 1u) && pos < 514) orow[pos] = vv;
            pos += (int)(km & 1u) + (int)(im & 1u);
            km >>= 1; im >>= 1; pk >>= 2;
        }
    }

    // ---- inserted symbols: rare per-lane bit loop
    {
        const TSched kInsS2 = mk_sched(kp[12], kp[13], kp[14]);
        uint32_t m = insmask;
        while (m) {
            const int i = __ffs(m) - 1; m &= m - 1u;
            const uint32_t below = (1u << i) - 1u;
            const int nk = __popc(keepmask & below);
            const uint32_t j = insbase + (uint32_t)(ofs + nk);
            const int pos = outofs + nk + __popc(insmask & below) + 1;
            const uint32_t sb = tff_bits(kInsS2, j, one);
            if (pos < 514) orow[pos] = (float)(sb & 3u) + 1.0f;
        }
    }

    // ---- tail padding: 0.0 (= -1 + 1)
    for (int p = total_out + lane; p < 514; p += 32) orow[p] = 0.0f;
}

extern "C" void kernel_launch(void* const* d_in, const int* in_sizes, int n_in,
                              void* d_out, int out_size) {
    const float* x = (const float*)d_in[0];   // segment_en [B, 512]
    float* out = (float*)d_out;               // [B, 4, 514] float32
    const int B = in_sizes[0] / 512;

    key_setup_kernel<<<1, 4>>>();

    const long long total_threads = (long long)B * 4 * 32;
    const int block = 128;
    const int grid = (int)((total_threads + block - 1) / block);
    channel_warp_kernel<<<grid, block>>>(x, out, B);
}

// round 17
// speedup vs baseline: 1.0044x; 1.0007x over previous
#include <cuda_runtime.h>
#include <cstdint>

// ============================================================================
// Bit-exact JAX threefry2x32 (partitionable) — rel_err = 0.0 verified R2-R16.
// R17 = R14/R16 (best: 323.7us, alu 93.3% = binder) + PRMT byte-rotates for
//   r=16 and r=24 (4 of 20 SHFs per threefry). Probe: if PRMT dispatches off
//   the alu pipe, alu/tf 41->37 (~-10% on the binder); if alu-pipe, neutral.
// ============================================================================

#define FULLM 0xffffffffu

struct TKey { uint32_t a, b, c; };

__device__ __forceinline__ TKey mk_key(uint32_t k0, uint32_t k1) {
    TKey k; k.a = k0; k.b = k1; k.c = k0 ^ k1 ^ 0x1BD11BDAu; return k;
}

// ---- plain threefry (setup kernel only)
#define TF_ROUND(x0, x1, r) { x0 += x1; x1 = __funnelshift_l(x1, x1, (r)); x1 ^= x0; }
#define TF_R4A(x0, x1) { TF_ROUND(x0,x1,13) TF_ROUND(x0,x1,15) TF_ROUND(x0,x1,26) TF_ROUND(x0,x1,6) }
#define TF_R4B(x0, x1) { TF_ROUND(x0,x1,17) TF_ROUND(x0,x1,29) TF_ROUND(x0,x1,16) TF_ROUND(x0,x1,24) }

__device__ __forceinline__ void tf_pair(const TKey k, uint32_t c0, uint32_t c1,
                                        uint32_t& o0, uint32_t& o1) {
    uint32_t x0 = c0 + k.a, x1 = c1 + k.b;
    TF_R4A(x0, x1); x0 += k.b; x1 += k.c + 1u;
    TF_R4B(x0, x1); x0 += k.c; x1 += k.a + 2u;
    TF_R4A(x0, x1); x0 += k.a; x1 += k.b + 3u;
    TF_R4B(x0, x1); x0 += k.b; x1 += k.c + 4u;
    TF_R4A(x0, x1); x0 += k.c; x1 += k.a + 5u;
    o0 = x0; o1 = x1;
}

// ---- add on the IMAD pipe (`one` = opaque runtime 1)
__device__ __forceinline__ uint32_t addf(uint32_t a, uint32_t b, uint32_t one) {
    uint32_t d;
    asm("mad.lo.u32 %0, %1, %2, %3;" : "=r"(d) : "r"(a), "r"(one), "r"(b));
    return d;
}

// ---- shift-and-accumulate on the IMAD pipe: d = a * mult + b  (mult = 2^k)
__device__ __forceinline__ uint32_t madp(uint32_t a, uint32_t mult, uint32_t b) {
    uint32_t d;
    asm("mad.lo.u32 %0, %1, %2, %3;" : "=r"(d) : "r"(a), "r"(mult), "r"(b));
    return d;
}

// ---- byte rotates via PRMT (exact rotl by 16 / 24 of a 32-bit word)
__device__ __forceinline__ uint32_t rot16p(uint32_t x) {
    uint32_t d;
    asm("prmt.b32 %0, %1, %1, 0x1032;" : "=r"(d) : "r"(x));
    return d;
}
__device__ __forceinline__ uint32_t rot24p(uint32_t x) {
    uint32_t d;
    asm("prmt.b32 %0, %1, %1, 0x0321;" : "=r"(d) : "r"(x));
    return d;
}

struct TSched {
    uint32_t a, b, c;
    uint32_t c1, a2, b3, c4, a5;   // k.c+1, k.a+2, k.b+3, k.c+4, k.a+5
};

__device__ __forceinline__ TSched mk_sched(uint32_t a, uint32_t b, uint32_t c) {
    TSched s; s.a = a; s.b = b; s.c = c;
    s.c1 = c + 1u; s.a2 = a + 2u; s.b3 = b + 3u; s.c4 = c + 4u; s.a5 = a + 5u;
    return s;
}

#define TFF_ROUND(x0, x1, r) { x0 = addf(x0, x1, one); x1 = __funnelshift_l(x1, x1, (r)); x1 ^= x0; }
#define TFF_ROUND16(x0, x1) { x0 = addf(x0, x1, one); x1 = rot16p(x1) ^ x0; }
#define TFF_ROUND24(x0, x1) { x0 = addf(x0, x1, one); x1 = rot24p(x1) ^ x0; }

#define TFF_R4A(x0, x1) { TFF_ROUND(x0,x1,13) TFF_ROUND(x0,x1,15) TFF_ROUND(x0,x1,26) TFF_ROUND(x0,x1,6) }
#define TFF_R4B(x0, x1) { TFF_ROUND(x0,x1,17) TFF_ROUND(x0,x1,29) TFF_ROUND16(x0,x1) TFF_ROUND24(x0,x1) }

// threefry2x32 at counter (0, idx): 16 SHF + 4 PRMT + 21 LOP3, 31 IMAD
__device__ __forceinline__ uint32_t tff_bits(const TSched k, uint32_t idx, uint32_t one) {
    uint32_t x0 = k.a, x1 = addf(idx, k.b, one);
    TFF_R4A(x0, x1); x0 = addf(x0, k.b, one); x1 = addf(x1, k.c1, one);
    TFF_R4B(x0, x1); x0 = addf(x0, k.c, one); x1 = addf(x1, k.a2, one);
    TFF_R4A(x0, x1); x0 = addf(x0, k.a, one); x1 = addf(x1, k.b3, one);
    TFF_R4B(x0, x1); x0 = addf(x0, k.b, one); x1 = addf(x1, k.c4, one);
    TFF_R4A(x0, x1); x0 = addf(x0, k.c, one); x1 = addf(x1, k.a5, one);
    return x0 ^ x1;
}

// Pre-shifted threshold: uniform(bits) < e  <=>  bits < (ceil(e*2^23) << 9).
__device__ __forceinline__ uint32_t thresh_shifted(float e) {
    return ((uint32_t)ceil((double)e * 8388608.0)) << 9;
}

// SWAR: per-2-bit-field (a + b) mod 4 over all 16 fields at once (4 LOP3).
__device__ __forceinline__ uint32_t add2bit_mod4(uint32_t a, uint32_t b) {
    const uint32_t t = a ^ b;
    const uint32_t cy = (a & b) & 0x55555555u;
    return t ^ (cy << 1);
}

// ============================================================================
// Per-channel key cache (keys depend only on channel c).
// ============================================================================

__device__ uint32_t g_keys[4][16];

__global__ void key_setup_kernel() {
    const int c = threadIdx.x;
    if (c >= 4) return;
    uint32_t t0, t1;
    const TKey root = mk_key(0u, 42u);
    tf_pair(root, 0u, (uint32_t)c, t0, t1);
    const TKey kc = mk_key(t0, t1);

    tf_pair(kc, 0u, 0u, t0, t1); const TKey s1 = mk_key(t0, t1);
    tf_pair(kc, 0u, 1u, t0, t1); const TKey s2 = mk_key(t0, t1);
    tf_pair(kc, 0u, 2u, t0, t1); const TKey s3 = mk_key(t0, t1);

    tf_pair(s1, 0u, 0u, t0, t1); const TKey sub_a = mk_key(t0, t1);
    tf_pair(sub_a, 0u, 1u, t0, t1); const TKey k_subdata = mk_key(t0, t1);
    tf_pair(s1, 0u, 1u, t0, t1); const TKey k_submask = mk_key(t0, t1);

    tf_pair(s3, 0u, 0u, t0, t1); const TKey k_insflag = mk_key(t0, t1);
    tf_pair(s3, 0u, 1u, t0, t1); const TKey ins_b = mk_key(t0, t1);
    tf_pair(ins_b, 0u, 1u, t0, t1); const TKey k_inssym = mk_key(t0, t1);

    uint32_t* kp = g_keys[c];
    kp[0] = k_submask.a; kp[1] = k_submask.b; kp[2] = k_submask.c;
    kp[3] = s2.a;        kp[4] = s2.b;        kp[5] = s2.c;
    kp[6] = k_subdata.a; kp[7] = k_subdata.b; kp[8] = k_subdata.c;
    kp[9] = k_insflag.a; kp[10] = k_insflag.b; kp[11] = k_insflag.c;
    kp[12] = k_inssym.a; kp[13] = k_inssym.b; kp[14] = k_inssym.c;
}

// ============================================================================
// Warp-per-(row, channel); lane owns 16 contiguous elements, 2-bit packed.
// ============================================================================

__global__ void __launch_bounds__(128)
channel_warp_kernel(const float* __restrict__ x, float* __restrict__ out, int B) {
    const int gw = (int)((blockIdx.x * blockDim.x + threadIdx.x) >> 5);
    const int lane = threadIdx.x & 31;
    if (gw >= B * 4) return;
    const int c = gw & 3;
    const int b = gw >> 2;

    const uint32_t KsubS = thresh_shifted(0.02f);
    const uint32_t KdelS = thresh_shifted(0.01f);
    const uint32_t KinsS = thresh_shifted(0.01f);

    const uint32_t* kp = g_keys[c];
    const uint32_t one = (kp[0] >> 31) | 1u;       // opaque runtime 1
    const TSched kSubM = mk_sched(kp[0], kp[1], kp[2]);
    const TSched kDel  = mk_sched(kp[3], kp[4], kp[5]);

    // ---- phase 1: sub-need + keep flags (unroll 4, ILP=8); no LDGs yet
    const uint32_t base = (uint32_t)b * 512u + (uint32_t)lane * 16u;
    uint32_t keepmask = 0u, subneed = 0u;
    {
        uint32_t bit = 1u;
        #pragma unroll 4
        for (int i = 0; i < 16; i++) {
            const uint32_t idx = base + (uint32_t)i;
            const uint32_t bs = tff_bits(kSubM, idx, one);
            const uint32_t bd = tff_bits(kDel,  idx, one);
            if (bs < KsubS)  subneed  |= bit;
            if (bd >= KdelS) keepmask |= bit;
            bit <<= 1;
        }
    }

    // ---- load input and pack to 2-bit codes (F2I + IMAD: all fma pipe)
    uint32_t vpack = 0u;
    {
        const float4* __restrict__ xr4 =
            (const float4*)(x + (size_t)b * 512 + (size_t)lane * 16);
        #pragma unroll
        for (int q = 0; q < 4; q++) {
            const float4 f = xr4[q];
            const uint32_t c0 = (uint32_t)__float2int_rn(f.x);
            const uint32_t c1 = (uint32_t)__float2int_rn(f.y);
            const uint32_t c2 = (uint32_t)__float2int_rn(f.z);
            const uint32_t c3 = (uint32_t)__float2int_rn(f.w);
            vpack = madp(c0, (1u << (8 * q + 0)) * one, vpack);
            vpack = madp(c1, (1u << (8 * q + 2)) * one, vpack);
            vpack = madp(c2, (1u << (8 * q + 4)) * one, vpack);
            vpack = madp(c3, (1u << (8 * q + 6)) * one, vpack);
        }
    }

    // ---- deferred sub draws: per-lane bit loop, 2-bit packed deltas
    uint32_t subdelta = 0u;
    {
        const TSched kSubD = mk_sched(kp[6], kp[7], kp[8]);
        uint32_t m = subneed;
        while (m) {
            const int i = __ffs(m) - 1; m &= m - 1u;
            const uint32_t db = tff_bits(kSubD, base + (uint32_t)i, one);
            subdelta |= (db & 3u) << (2 * i);
        }
    }
    uint32_t pk = add2bit_mod4(vpack, subdelta);

    // ---- scan 1: exclusive scan of keep counts -> compacted offset
    const int kn = __popc(keepmask);
    int incl = kn;
    #pragma unroll
    for (int d = 1; d < 32; d <<= 1) {
        const int nv = __shfl_up_sync(FULLM, incl, d);
        if (lane >= d) incl += nv;
    }
    const int ofs = incl - kn;

    // ---- phase 2: ins flags at compacted indices (iterative j, unroll 4)
    const uint32_t insbase = (uint32_t)b * 514u;
    uint32_t insmask = 0u;
    {
        const TSched kInsF = mk_sched(kp[9], kp[10], kp[11]);
        uint32_t km = keepmask, bit = 1u;
        uint32_t j = insbase + (uint32_t)ofs;
        #pragma unroll 4
        for (int i = 0; i < 16; i++) {
            const uint32_t bi = tff_bits(kInsF, j, one);
            if (bi < KinsS) insmask |= bit;
            j += km & 1u; km >>= 1; bit <<= 1;
        }
    }
    insmask &= keepmask;

    // ---- scan 2: output offsets
    const int myout = kn + __popc(insmask);
    int incl2 = myout;
    #pragma unroll
    for (int d = 1; d < 32; d <<= 1) {
        const int nv = __shfl_up_sync(FULLM, incl2, d);
        if (lane >= d) incl2 += nv;
    }
    const int outofs = incl2 - myout;
    const int total_out = __shfl_sync(FULLM, incl2, 31);

    float* __restrict__ orow = out + ((size_t)b * 4 + (size_t)c) * 514;

    // ---- write kept elements: extract 2-bit code -> I2F + FADD (fma pipe)
    {
        int pos = outofs;
        uint32_t km = keepmask, im = insmask;
        #pragma unroll
        for (int i = 0; i < 16; i++) {
            const float vv = (float)(pk & 3u) + 1.0f;   // code in [0,3] exact
            if ((km & 1u) && pos < 514) orow[pos] = vv;
            pos += (int)(km & 1u) + (int)(im & 1u);
            km >>= 1; im >>= 1; pk >>= 2;
        }
    }

    // ---- inserted symbols: rare per-lane bit loop
    {
        const TSched kInsS2 = mk_sched(kp[12], kp[13], kp[14]);
        uint32_t m = insmask;
        while (m) {
            const int i = __ffs(m) - 1; m &= m - 1u;
            const uint32_t below = (1u << i) - 1u;
            const int nk = __popc(keepmask & below);
            const uint32_t j = insbase + (uint32_t)(ofs + nk);
            const int pos = outofs + nk + __popc(insmask & below) + 1;
            const uint32_t sb = tff_bits(kInsS2, j, one);
            if (pos < 514) orow[pos] = (float)(sb & 3u) + 1.0f;
        }
    }

    // ---- tail padding: 0.0 (= -1 + 1)
    for (int p = total_out + lane; p < 514; p += 32) orow[p] = 0.0f;
}

extern "C" void kernel_launch(void* const* d_in, const int* in_sizes, int n_in,
                              void* d_out, int out_size) {
    const float* x = (const float*)d_in[0];   // segment_en [B, 512]
    float* out = (float*)d_out;               // [B, 4, 514] float32
    const int B = in_sizes[0] / 512;

    key_setup_kernel<<<1, 4>>>();

    const long long total_threads = (long long)B * 4 * 32;
    const int block = 128;
    const int grid = (int)((total_threads + block - 1) / block);
    channel_warp_kernel<<<grid, block>>>(x, out, B);
}